// round 14
// baseline (speedup 1.0000x reference)
#include <cuda_runtime.h>
#include <cuda_bf16.h>
#include <math.h>

#define N_NODES   100000
#define N_EDGES   3200000
#define N_GRAPHS  512
#define FEAT      128
#define H1DIM     32
#define H2DIM     16
#define NCLS      10

#define SB        1024
#define NBLK      ((N_NODES + SB - 1) / SB)    // 98

#define G1ROWS    32
#define G1PAD     132

// ---------------- scratch ---------------------------------------------------
__device__ __align__(16)  int   g_degi  [N_NODES];
__device__ __align__(16)  int   g_rowptr[N_NODES + 1];
__device__ __align__(16)  int   g_cursor[N_NODES];
__device__ __align__(16)  int   g_csrc  [N_EDGES];
__device__ __align__(16)  int   g_bsum  [NBLK];
__device__ __align__(16)  int   g_bbase [NBLK];
__device__ __align__(16)  float g_dinv  [N_NODES];
__device__ __align__(128) float g_h1s   [N_NODES * H1DIM];
__device__ __align__(128) float g_h2s   [N_NODES * H2DIM];
__device__ __align__(16)  float g_sum   [N_GRAPHS * H2DIM];
__device__ __align__(16)  float g_cnt   [N_GRAPHS];
__device__ int g_ei64;
__device__ int g_bat64;

__device__ __forceinline__ int clampi(int v, int lo, int hi) {
    return v < lo ? lo : (v > hi ? hi : v);
}

__device__ __forceinline__ float tf32r(float v) {
    unsigned r;
    asm("cvt.rna.tf32.f32 %0, %1;" : "=r"(r) : "f"(v));
    return __uint_as_float(r);
}

__device__ __forceinline__ int load_idx(const void* p, long long i, int is64) {
    if (is64) return (int)((const long long*)p)[i];
    return ((const int*)p)[i];
}

// ---------------- 0. probe dtypes ------------------------------------------
__global__ void k_probe(const int* __restrict__ ei32, const int* __restrict__ bat32) {
    if (threadIdx.x == 0) {
        int all0 = 1;
        for (int k = 0; k < 64; k++) if (ei32[2 * k + 1] != 0) { all0 = 0; break; }
        g_ei64 = all0;
        int all0b = 1;
        for (int k = 40000; k < 40064; k++)
            if (bat32[2 * k + 1] != 0) { all0b = 0; break; }
        g_bat64 = all0b;
    }
}

// ---------------- 1. init --------------------------------------------------
__global__ void k_init(void) {
    int i = blockIdx.x * blockDim.x + threadIdx.x;
    if (i < N_NODES) g_degi[i] = 0;
    if (i < N_GRAPHS * H2DIM) g_sum[i] = 0.0f;
    if (i < N_GRAPHS) g_cnt[i] = 0.0f;
}

// ---------------- 2. in-degree (2 edges per thread) ------------------------
__global__ void k_deg(const void* __restrict__ ei) {
    int t = blockIdx.x * blockDim.x + threadIdx.x;
    int is64 = g_ei64;
    int e = 2 * t;
    if (e + 1 < N_EDGES) {
        int d0, d1;
        if (is64) {
            longlong2 v = ((const longlong2*)ei)[(N_EDGES / 2) + t];
            d0 = (int)v.x; d1 = (int)v.y;
        } else {
            int2 v = ((const int2*)ei)[(N_EDGES / 2) + t];
            d0 = v.x; d1 = v.y;
        }
        atomicAdd(&g_degi[clampi(d0, 0, N_NODES - 1)], 1);
        atomicAdd(&g_degi[clampi(d1, 0, N_NODES - 1)], 1);
    } else if (e < N_EDGES) {
        int d = clampi(load_idx(ei, (long long)N_EDGES + e, is64), 0, N_NODES - 1);
        atomicAdd(&g_degi[d], 1);
    }
}

// ---------------- 3a. block sums -------------------------------------------
__global__ void k_bsum(void) {
    __shared__ int swarp[SB / 32];
    int tid = threadIdx.x;
    int i = blockIdx.x * SB + tid;
    int v = (i < N_NODES) ? g_degi[i] : 0;
    for (int off = 16; off > 0; off >>= 1) v += __shfl_down_sync(0xffffffffu, v, off);
    if ((tid & 31) == 0) swarp[tid >> 5] = v;
    __syncthreads();
    if (tid < SB / 32) {
        int w = swarp[tid];
        for (int off = SB / 64; off > 0; off >>= 1) w += __shfl_down_sync(0xffffffffu, w, off);
        if (tid == 0) g_bsum[blockIdx.x] = w;
    }
}

// ---------------- 3b. scan block sums --------------------------------------
__global__ void k_bscan(void) {
    __shared__ int s[128];
    int t = threadIdx.x;
    int v = (t < NBLK) ? g_bsum[t] : 0;
    s[t] = v;
    __syncthreads();
    for (int off = 1; off < 128; off <<= 1) {
        int u = (t >= off) ? s[t - off] : 0;
        __syncthreads();
        s[t] += u;
        __syncthreads();
    }
    if (t < NBLK) g_bbase[t] = s[t] - v;
}

// ---------- 3c. rowptr + cursor + dinv (warp-shuffle scan) -----------------
__global__ void k_rowfill(void) {
    __shared__ int swsum[SB / 32];
    int tid  = threadIdx.x;
    int lane = tid & 31, wid = tid >> 5;
    int i = blockIdx.x * SB + tid;
    int v = (i < N_NODES) ? g_degi[i] : 0;
    int incl = v;
    for (int off = 1; off < 32; off <<= 1) {
        int u = __shfl_up_sync(0xffffffffu, incl, off);
        if (lane >= off) incl += u;
    }
    if (lane == 31) swsum[wid] = incl;
    __syncthreads();
    if (wid == 0) {
        int w = (lane < SB / 32) ? swsum[lane] : 0;
        for (int off = 1; off < 32; off <<= 1) {
            int u = __shfl_up_sync(0xffffffffu, w, off);
            if (lane >= off) w += u;
        }
        if (lane < SB / 32) swsum[lane] = w;
    }
    __syncthreads();
    int warpBase = (wid == 0) ? 0 : swsum[wid - 1];
    int base = g_bbase[blockIdx.x];
    if (i < N_NODES) {
        int r = base + warpBase + incl - v;
        g_rowptr[i] = r;
        g_cursor[i] = r;
        g_dinv[i]   = rsqrtf((float)(v + 1));
        if (i == N_NODES - 1) g_rowptr[N_NODES] = base + warpBase + incl;
    }
}

// ---------------- 5. CSR fill: src only ------------------------------------
__global__ void k_fill(const void* __restrict__ ei) {
    int e = blockIdx.x * blockDim.x + threadIdx.x;
    int is64 = g_ei64;
    if (e < N_EDGES) {
        int s = clampi(load_idx(ei, e, is64), 0, N_NODES - 1);
        int d = clampi(load_idx(ei, (long long)N_EDGES + e, is64), 0, N_NODES - 1);
        int pos = atomicAdd(&g_cursor[d], 1);
        g_csrc[clampi(pos, 0, N_EDGES - 1)] = s;
    }
}

// ------- 6. GEMM1 tiled: h1s = (X @ W1) * dinv  (thread = 4 outputs) -------
__global__ void k_gemm1(const float* __restrict__ x, const float* __restrict__ W1) {
    __shared__ float sX [G1ROWS * G1PAD];
    __shared__ float sWT[H1DIM * G1PAD];
    int tid = threadIdx.x;
    int rowBase = blockIdx.x * G1ROWS;
    for (int i = tid; i < FEAT * H1DIM; i += 256) {
        int k = i >> 5, j = i & 31;
        sWT[j * G1PAD + k] = tf32r(W1[i]);
    }
    for (int q = tid; q < G1ROWS * (FEAT / 4); q += 256) {
        int row = q >> 5, kq = q & 31;
        float4 v = reinterpret_cast<const float4*>(x)[(rowBase + row) * (FEAT / 4) + kq];
        v.x = tf32r(v.x); v.y = tf32r(v.y); v.z = tf32r(v.z); v.w = tf32r(v.w);
        *reinterpret_cast<float4*>(&sX[row * G1PAD + kq * 4]) = v;
    }
    __syncthreads();
    int r  = tid >> 3;
    int jg = tid & 7;
    float a0 = 0.f, a1 = 0.f, a2 = 0.f, a3 = 0.f;
    const float* xr = &sX[r * G1PAD];
    const float* w0 = &sWT[jg * G1PAD];
    const float* w1 = &sWT[(jg + 8) * G1PAD];
    const float* w2 = &sWT[(jg + 16) * G1PAD];
    const float* w3 = &sWT[(jg + 24) * G1PAD];
#pragma unroll
    for (int kq = 0; kq < FEAT / 4; kq++) {
        float4 xv = *reinterpret_cast<const float4*>(&xr[kq * 4]);
        float4 q0 = *reinterpret_cast<const float4*>(&w0[kq * 4]);
        float4 q1 = *reinterpret_cast<const float4*>(&w1[kq * 4]);
        float4 q2 = *reinterpret_cast<const float4*>(&w2[kq * 4]);
        float4 q3 = *reinterpret_cast<const float4*>(&w3[kq * 4]);
        a0 = fmaf(xv.x, q0.x, a0); a0 = fmaf(xv.y, q0.y, a0);
        a0 = fmaf(xv.z, q0.z, a0); a0 = fmaf(xv.w, q0.w, a0);
        a1 = fmaf(xv.x, q1.x, a1); a1 = fmaf(xv.y, q1.y, a1);
        a1 = fmaf(xv.z, q1.z, a1); a1 = fmaf(xv.w, q1.w, a1);
        a2 = fmaf(xv.x, q2.x, a2); a2 = fmaf(xv.y, q2.y, a2);
        a2 = fmaf(xv.z, q2.z, a2); a2 = fmaf(xv.w, q2.w, a2);
        a3 = fmaf(xv.x, q3.x, a3); a3 = fmaf(xv.y, q3.y, a3);
        a3 = fmaf(xv.z, q3.z, a3); a3 = fmaf(xv.w, q3.w, a3);
    }
    int row = rowBase + r;
    float dv = g_dinv[row];
    float* dst = &g_h1s[row * H1DIM];
    dst[jg]      = a0 * dv;
    dst[jg + 8]  = a1 * dv;
    dst[jg + 16] = a2 * dv;
    dst[jg + 24] = a3 * dv;
}

// ------- 7. FUSED agg1 + bias1 + relu + GEMM2 -> h2s (warp per node) -------
__global__ void k_agg1g2(const float* __restrict__ b1, const float* __restrict__ W2) {
    __shared__ float sW[H1DIM * H2DIM];
    __shared__ float sb[H1DIM];
    for (int i = threadIdx.x; i < H1DIM * H2DIM; i += blockDim.x) sW[i] = tf32r(W2[i]);
    if (threadIdx.x < H1DIM) sb[threadIdx.x] = b1[threadIdx.x];
    __syncthreads();
    int warp = (blockIdx.x * blockDim.x + threadIdx.x) >> 5;
    int lane = threadIdx.x & 31;
    if (warp >= N_NODES) return;
    int d = warp;
    int start = g_rowptr[d], end = g_rowptr[d + 1];
    float dvd = g_dinv[d];
    float acc = g_h1s[d * H1DIM + lane];          // self loop (pre-scaled)
    for (int base = start; base < end; base += 32) {
        int n = end - base;
        int s = (lane < n) ? g_csrc[base + lane] : 0;
        int m = n < 32 ? n : 32;
        float a0 = 0.f, a1 = 0.f, a2 = 0.f, a3 = 0.f;
#pragma unroll
        for (int j = 0; j < 32; j += 4) {
            int s0 = __shfl_sync(0xffffffffu, s, j);
            int s1 = __shfl_sync(0xffffffffu, s, j + 1);
            int s2 = __shfl_sync(0xffffffffu, s, j + 2);
            int s3 = __shfl_sync(0xffffffffu, s, j + 3);
            if (j     < m) a0 += g_h1s[s0 * H1DIM + lane];
            if (j + 1 < m) a1 += g_h1s[s1 * H1DIM + lane];
            if (j + 2 < m) a2 += g_h1s[s2 * H1DIM + lane];
            if (j + 3 < m) a3 += g_h1s[s3 * H1DIM + lane];
        }
        acc += (a0 + a1) + (a2 + a3);
    }
    float v = tf32r(fmaxf(acc * dvd + sb[lane], 0.0f));
    int j = lane & 15;
    float acc2 = 0.0f;
#pragma unroll
    for (int r = 0; r < 32; r++) {
        float xb = __shfl_sync(0xffffffffu, v, r);
        acc2 = fmaf(xb, sW[r * H2DIM + j], acc2);
    }
    if (lane < H2DIM) g_h2s[d * H2DIM + lane] = acc2 * dvd;
}

// ---- 8. FUSED agg2 + bias2 + relu + pool (TWO nodes per warp) -------------
__global__ void k_agg2pool(const float* __restrict__ b2, const void* __restrict__ batch) {
    int warp = (blockIdx.x * blockDim.x + threadIdx.x) >> 5;
    int lane = threadIdx.x & 31;
    int is64 = g_bat64;
    int d = 2 * warp + (lane >> 4);
    int l = lane & 15;
    if (d >= N_NODES) return;              // N_NODES even -> warp-uniform exit
    int start = g_rowptr[d], end = g_rowptr[d + 1];
    int total = end - start;
    float dvd = g_dinv[d];
    float acc = g_h2s[d * H2DIM + l];
    int iters = (total + 15) >> 4;
    int maxIters = __reduce_max_sync(0xffffffffu, iters);
    for (int t = 0; t < maxIters; t++) {
        int idx = start + t * 16 + l;
        int s = (idx < end) ? g_csrc[idx] : 0;
        int done = t * 16;
        int m = total - done; if (m > 16) m = 16; if (m < 0) m = 0;
        float a0 = 0.f, a1 = 0.f, a2 = 0.f, a3 = 0.f;
#pragma unroll
        for (int j = 0; j < 16; j += 4) {
            int s0 = __shfl_sync(0xffffffffu, s, j,     16);
            int s1 = __shfl_sync(0xffffffffu, s, j + 1, 16);
            int s2 = __shfl_sync(0xffffffffu, s, j + 2, 16);
            int s3 = __shfl_sync(0xffffffffu, s, j + 3, 16);
            if (j     < m) a0 += g_h2s[s0 * H2DIM + l];
            if (j + 1 < m) a1 += g_h2s[s1 * H2DIM + l];
            if (j + 2 < m) a2 += g_h2s[s2 * H2DIM + l];
            if (j + 3 < m) a3 += g_h2s[s3 * H2DIM + l];
        }
        acc += (a0 + a1) + (a2 + a3);
    }
    int g = clampi(load_idx(batch, d, is64), 0, N_GRAPHS - 1);
    float v = fmaxf(acc * dvd + b2[l], 0.0f);
    atomicAdd(&g_sum[g * H2DIM + l], v);
    if (l == 0) atomicAdd(&g_cnt[g], 1.0f);
}

// ---------------- 11. final: mean, FC (tf32), softmax ----------------------
__global__ void k_final(const float* __restrict__ fc_w, const float* __restrict__ fc_b,
                        float* __restrict__ out) {
    int g = blockIdx.x * blockDim.x + threadIdx.x;
    if (g >= N_GRAPHS) return;
    float inv = 1.0f / fmaxf(g_cnt[g], 1.0f);
    float p[H2DIM];
#pragma unroll
    for (int j = 0; j < H2DIM; j++) p[j] = tf32r(g_sum[g * H2DIM + j] * inv);
    float logit[NCLS];
#pragma unroll
    for (int c = 0; c < NCLS; c++) {
        float acc = 0.0f;
#pragma unroll
        for (int j = 0; j < H2DIM; j++) acc = fmaf(p[j], tf32r(fc_w[j * NCLS + c]), acc);
        logit[c] = acc + fc_b[c];
    }
    float m = logit[0];
#pragma unroll
    for (int c = 1; c < NCLS; c++) m = fmaxf(m, logit[c]);
    float s = 0.0f;
#pragma unroll
    for (int c = 0; c < NCLS; c++) { logit[c] = expf(logit[c] - m); s += logit[c]; }
    float invs = 1.0f / s;
#pragma unroll
    for (int c = 0; c < NCLS; c++) out[g * NCLS + c] = logit[c] * invs;
}

// ---------------------------------------------------------------------------
extern "C" void kernel_launch(void* const* d_in, const int* in_sizes, int n_in,
                              void* d_out, int out_size) {
    const float *x   = (n_in > 0) ? (const float*)d_in[0] : 0;
    const void  *ei  = (n_in > 1) ? d_in[1]               : 0;
    const void  *bat = (n_in > 2) ? d_in[2]               : 0;
    const float *W1  = (n_in > 3) ? (const float*)d_in[3] : 0;
    const float *b1  = (n_in > 4) ? (const float*)d_in[4] : 0;
    const float *W2  = (n_in > 5) ? (const float*)d_in[5] : 0;
    const float *b2  = (n_in > 6) ? (const float*)d_in[6] : 0;
    const float *fcw = (n_in > 7) ? (const float*)d_in[7] : 0;
    const float *fcb = (n_in > 8) ? (const float*)d_in[8] : 0;

    for (int i = 0; i < n_in; i++) {
        switch (in_sizes[i]) {
            case N_NODES * FEAT:   x   = (const float*)d_in[i]; break;
            case 2 * N_EDGES:      ei  = d_in[i];               break;
            case N_NODES:          bat = d_in[i];               break;
            case FEAT * H1DIM:     W1  = (const float*)d_in[i]; break;
            case H1DIM:            b1  = (const float*)d_in[i]; break;
            case H1DIM * H2DIM:    W2  = (const float*)d_in[i]; break;
            case H2DIM:            b2  = (const float*)d_in[i]; break;
            case H2DIM * NCLS:     fcw = (const float*)d_in[i]; break;
            case NCLS:             fcb = (const float*)d_in[i]; break;
            default: break;
        }
    }
    float* out = (float*)d_out;
    if (!x || !ei || !bat || !W1 || !b1 || !W2 || !b2 || !fcw || !fcb || !out) return;

    const int T = 256;
    k_probe   <<<1, 32>>>((const int*)ei, (const int*)bat);                 // 0
    k_init    <<<(N_NODES + T - 1) / T, T>>>();                             // 1
    k_deg     <<<(N_EDGES / 2 + T - 1) / T, T>>>(ei);                       // 2
    // DIAGNOSTIC: duplicate agg1g2 at profiled launch slot (index 3).
    // Reads steady-state scratch from previous replay; h2s is overwritten by
    // the real agg1g2 below, so the final output is unaffected.
    k_agg1g2  <<<(N_NODES * 32 + T - 1) / T, T>>>(b1, W2);                  // 3 <- ncu
    k_bsum    <<<NBLK, SB>>>();
    k_bscan   <<<1, 128>>>();
    k_rowfill <<<NBLK, SB>>>();
    k_fill    <<<(N_EDGES + T - 1) / T, T>>>(ei);
    k_gemm1   <<<N_NODES / G1ROWS, 256>>>(x, W1);
    k_agg1g2  <<<(N_NODES * 32 + T - 1) / T, T>>>(b1, W2);
    k_agg2pool<<<(N_NODES / 2 * 32 + T - 1) / T, T>>>(b2, bat);
    k_final   <<<(N_GRAPHS + T - 1) / T, T>>>(fcw, fcb, out);
}

// round 15
// speedup vs baseline: 1.3114x; 1.3114x over previous
#include <cuda_runtime.h>
#include <cuda_bf16.h>
#include <math.h>

#define N_NODES   100000
#define N_EDGES   3200000
#define N_GRAPHS  512
#define FEAT      128
#define H1DIM     32
#define H2DIM     16
#define NCLS      10

#define SB        1024
#define NBLK      ((N_NODES + SB - 1) / SB)    // 98

#define G1ROWS    32
#define G1PAD     132

// ---------------- scratch ---------------------------------------------------
__device__ __align__(16)  int   g_degi  [N_NODES];
__device__ __align__(16)  int   g_rowptr[N_NODES + 1];
__device__ __align__(16)  int   g_epos  [N_EDGES];       // edge position within dst bucket
__device__ __align__(16)  int   g_csrc  [N_EDGES];       // CSR src (dst-sorted)
__device__ __align__(16)  int   g_bsum  [NBLK];
__device__ __align__(16)  int   g_bbase [NBLK];
__device__ __align__(16)  float g_dinv  [N_NODES];
__device__ __align__(128) float g_h1s   [N_NODES * H1DIM];
__device__ __align__(128) float g_h2s   [N_NODES * H2DIM];
__device__ __align__(16)  float g_sum   [N_GRAPHS * H2DIM];
__device__ __align__(16)  float g_cnt   [N_GRAPHS];
__device__ int g_ei64;
__device__ int g_bat64;

__device__ __forceinline__ int clampi(int v, int lo, int hi) {
    return v < lo ? lo : (v > hi ? hi : v);
}

__device__ __forceinline__ float tf32r(float v) {
    unsigned r;
    asm("cvt.rna.tf32.f32 %0, %1;" : "=r"(r) : "f"(v));
    return __uint_as_float(r);
}

__device__ __forceinline__ int load_idx(const void* p, long long i, int is64) {
    if (is64) return (int)((const long long*)p)[i];
    return ((const int*)p)[i];
}

// ---------------- 0. probe dtypes ------------------------------------------
__global__ void k_probe(const int* __restrict__ ei32, const int* __restrict__ bat32) {
    if (threadIdx.x == 0) {
        int all0 = 1;
        for (int k = 0; k < 64; k++) if (ei32[2 * k + 1] != 0) { all0 = 0; break; }
        g_ei64 = all0;
        int all0b = 1;
        for (int k = 40000; k < 40064; k++)
            if (bat32[2 * k + 1] != 0) { all0b = 0; break; }
        g_bat64 = all0b;
    }
}

// ---------------- 1. init --------------------------------------------------
__global__ void k_init(void) {
    int i = blockIdx.x * blockDim.x + threadIdx.x;
    if (i < N_NODES) g_degi[i] = 0;
    if (i < N_GRAPHS * H2DIM) g_sum[i] = 0.0f;
    if (i < N_GRAPHS) g_cnt[i] = 0.0f;
}

// ------- 2. in-degree + per-edge bucket position (returning atomic) --------
__global__ void k_deg(const void* __restrict__ ei) {
    int t = blockIdx.x * blockDim.x + threadIdx.x;
    int is64 = g_ei64;
    int e = 2 * t;
    if (e + 1 < N_EDGES) {
        int d0, d1;
        if (is64) {
            longlong2 v = ((const longlong2*)ei)[(N_EDGES / 2) + t];
            d0 = (int)v.x; d1 = (int)v.y;
        } else {
            int2 v = ((const int2*)ei)[(N_EDGES / 2) + t];
            d0 = v.x; d1 = v.y;
        }
        int p0 = atomicAdd(&g_degi[clampi(d0, 0, N_NODES - 1)], 1);
        int p1 = atomicAdd(&g_degi[clampi(d1, 0, N_NODES - 1)], 1);
        g_epos[e]     = p0;
        g_epos[e + 1] = p1;
    } else if (e < N_EDGES) {
        int d = clampi(load_idx(ei, (long long)N_EDGES + e, is64), 0, N_NODES - 1);
        g_epos[e] = atomicAdd(&g_degi[d], 1);
    }
}

// ---------------- 3a. block sums -------------------------------------------
__global__ void k_bsum(void) {
    __shared__ int swarp[SB / 32];
    int tid = threadIdx.x;
    int i = blockIdx.x * SB + tid;
    int v = (i < N_NODES) ? g_degi[i] : 0;
    for (int off = 16; off > 0; off >>= 1) v += __shfl_down_sync(0xffffffffu, v, off);
    if ((tid & 31) == 0) swarp[tid >> 5] = v;
    __syncthreads();
    if (tid < SB / 32) {
        int w = swarp[tid];
        for (int off = SB / 64; off > 0; off >>= 1) w += __shfl_down_sync(0xffffffffu, w, off);
        if (tid == 0) g_bsum[blockIdx.x] = w;
    }
}

// ---------------- 3b. scan block sums --------------------------------------
__global__ void k_bscan(void) {
    __shared__ int s[128];
    int t = threadIdx.x;
    int v = (t < NBLK) ? g_bsum[t] : 0;
    s[t] = v;
    __syncthreads();
    for (int off = 1; off < 128; off <<= 1) {
        int u = (t >= off) ? s[t - off] : 0;
        __syncthreads();
        s[t] += u;
        __syncthreads();
    }
    if (t < NBLK) g_bbase[t] = s[t] - v;
}

// ---------- 3c. rowptr + dinv (warp-shuffle scan) --------------------------
__global__ void k_rowfill(void) {
    __shared__ int swsum[SB / 32];
    int tid  = threadIdx.x;
    int lane = tid & 31, wid = tid >> 5;
    int i = blockIdx.x * SB + tid;
    int v = (i < N_NODES) ? g_degi[i] : 0;
    int incl = v;
    for (int off = 1; off < 32; off <<= 1) {
        int u = __shfl_up_sync(0xffffffffu, incl, off);
        if (lane >= off) incl += u;
    }
    if (lane == 31) swsum[wid] = incl;
    __syncthreads();
    if (wid == 0) {
        int w = (lane < SB / 32) ? swsum[lane] : 0;
        for (int off = 1; off < 32; off <<= 1) {
            int u = __shfl_up_sync(0xffffffffu, w, off);
            if (lane >= off) w += u;
        }
        if (lane < SB / 32) swsum[lane] = w;
    }
    __syncthreads();
    int warpBase = (wid == 0) ? 0 : swsum[wid - 1];
    int base = g_bbase[blockIdx.x];
    if (i < N_NODES) {
        int r = base + warpBase + incl - v;
        g_rowptr[i] = r;
        g_dinv[i]   = rsqrtf((float)(v + 1));
        if (i == N_NODES - 1) g_rowptr[N_NODES] = base + warpBase + incl;
    }
}

// ---------------- 5. CSR fill: NO atomics ----------------------------------
__global__ void k_fill(const void* __restrict__ ei) {
    int e = blockIdx.x * blockDim.x + threadIdx.x;
    int is64 = g_ei64;
    if (e < N_EDGES) {
        int s = clampi(load_idx(ei, e, is64), 0, N_NODES - 1);
        int d = clampi(load_idx(ei, (long long)N_EDGES + e, is64), 0, N_NODES - 1);
        int pos = g_rowptr[d] + g_epos[e];
        g_csrc[clampi(pos, 0, N_EDGES - 1)] = s;
    }
}

// ------- 6. GEMM1 tiled: h1s = (X @ W1) * dinv  (thread = 4 outputs) -------
__global__ void k_gemm1(const float* __restrict__ x, const float* __restrict__ W1) {
    __shared__ float sX [G1ROWS * G1PAD];
    __shared__ float sWT[H1DIM * G1PAD];
    int tid = threadIdx.x;
    int rowBase = blockIdx.x * G1ROWS;
    for (int i = tid; i < FEAT * H1DIM; i += 256) {
        int k = i >> 5, j = i & 31;
        sWT[j * G1PAD + k] = tf32r(W1[i]);
    }
    for (int q = tid; q < G1ROWS * (FEAT / 4); q += 256) {
        int row = q >> 5, kq = q & 31;
        float4 v = reinterpret_cast<const float4*>(x)[(rowBase + row) * (FEAT / 4) + kq];
        v.x = tf32r(v.x); v.y = tf32r(v.y); v.z = tf32r(v.z); v.w = tf32r(v.w);
        *reinterpret_cast<float4*>(&sX[row * G1PAD + kq * 4]) = v;
    }
    __syncthreads();
    int r  = tid >> 3;
    int jg = tid & 7;
    float a0 = 0.f, a1 = 0.f, a2 = 0.f, a3 = 0.f;
    const float* xr = &sX[r * G1PAD];
    const float* w0 = &sWT[jg * G1PAD];
    const float* w1 = &sWT[(jg + 8) * G1PAD];
    const float* w2 = &sWT[(jg + 16) * G1PAD];
    const float* w3 = &sWT[(jg + 24) * G1PAD];
#pragma unroll
    for (int kq = 0; kq < FEAT / 4; kq++) {
        float4 xv = *reinterpret_cast<const float4*>(&xr[kq * 4]);
        float4 q0 = *reinterpret_cast<const float4*>(&w0[kq * 4]);
        float4 q1 = *reinterpret_cast<const float4*>(&w1[kq * 4]);
        float4 q2 = *reinterpret_cast<const float4*>(&w2[kq * 4]);
        float4 q3 = *reinterpret_cast<const float4*>(&w3[kq * 4]);
        a0 = fmaf(xv.x, q0.x, a0); a0 = fmaf(xv.y, q0.y, a0);
        a0 = fmaf(xv.z, q0.z, a0); a0 = fmaf(xv.w, q0.w, a0);
        a1 = fmaf(xv.x, q1.x, a1); a1 = fmaf(xv.y, q1.y, a1);
        a1 = fmaf(xv.z, q1.z, a1); a1 = fmaf(xv.w, q1.w, a1);
        a2 = fmaf(xv.x, q2.x, a2); a2 = fmaf(xv.y, q2.y, a2);
        a2 = fmaf(xv.z, q2.z, a2); a2 = fmaf(xv.w, q2.w, a2);
        a3 = fmaf(xv.x, q3.x, a3); a3 = fmaf(xv.y, q3.y, a3);
        a3 = fmaf(xv.z, q3.z, a3); a3 = fmaf(xv.w, q3.w, a3);
    }
    int row = rowBase + r;
    float dv = g_dinv[row];
    float* dst = &g_h1s[row * H1DIM];
    dst[jg]      = a0 * dv;
    dst[jg + 8]  = a1 * dv;
    dst[jg + 16] = a2 * dv;
    dst[jg + 24] = a3 * dv;
}

// ------- 7. FUSED agg1 + bias1 + relu + GEMM2 -> h2s -----------------------
// float2 gather: lanes 0-15 process even edges, 16-31 odd edges, 2 cols/lane.
__global__ void k_agg1g2(const float* __restrict__ b1, const float* __restrict__ W2) {
    __shared__ float sW[H1DIM * H2DIM];
    __shared__ float sb[H1DIM];
    for (int i = threadIdx.x; i < H1DIM * H2DIM; i += blockDim.x) sW[i] = tf32r(W2[i]);
    if (threadIdx.x < H1DIM) sb[threadIdx.x] = b1[threadIdx.x];
    __syncthreads();
    int warp = (blockIdx.x * blockDim.x + threadIdx.x) >> 5;
    int lane = threadIdx.x & 31;
    if (warp >= N_NODES) return;
    int d = warp;
    int start = g_rowptr[d], end = g_rowptr[d + 1];
    float dvd = g_dinv[d];
    int half = lane >> 4;                  // 0: even edges, 1: odd edges
    int cl   = lane & 15;                  // column pair index (cols 2cl, 2cl+1)
    const float2* h1s2 = reinterpret_cast<const float2*>(g_h1s);
    float2 acc;
    if (half == 0) {                       // self loop counted once (lower half)
        acc = h1s2[d * (H1DIM / 2) + cl];
    } else {
        acc.x = 0.f; acc.y = 0.f;
    }
    for (int base = start; base < end; base += 32) {
        int n = end - base;
        int s = (lane < n) ? g_csrc[base + lane] : 0;
        int m = n < 32 ? n : 32;
#pragma unroll
        for (int j = 0; j < 32; j += 2) {
            int je = j + half;             // this half's edge within chunk
            int sj = __shfl_sync(0xffffffffu, s, je);
            if (je < m) {
                float2 v = h1s2[sj * (H1DIM / 2) + cl];
                acc.x += v.x; acc.y += v.y;
            }
        }
    }
    // combine halves: lanes l and l+16 hold same column pair
    acc.x += __shfl_xor_sync(0xffffffffu, acc.x, 16);
    acc.y += __shfl_xor_sync(0xffffffffu, acc.y, 16);
    // redistribute to one column per lane: col = lane
    int src = lane >> 1;
    float ax = __shfl_sync(0xffffffffu, acc.x, src);
    float ay = __shfl_sync(0xffffffffu, acc.y, src);
    float a = (lane & 1) ? ay : ax;
    float v = tf32r(fmaxf(a * dvd + sb[lane], 0.0f));
    int j = lane & 15;
    float acc2 = 0.0f;
#pragma unroll
    for (int r = 0; r < 32; r++) {
        float xb = __shfl_sync(0xffffffffu, v, r);
        acc2 = fmaf(xb, sW[r * H2DIM + j], acc2);
    }
    if (lane < H2DIM) g_h2s[d * H2DIM + lane] = acc2 * dvd;
}

// ---- 8. FUSED agg2 + bias2 + relu + pool (TWO nodes per warp) -------------
__global__ void k_agg2pool(const float* __restrict__ b2, const void* __restrict__ batch) {
    int warp = (blockIdx.x * blockDim.x + threadIdx.x) >> 5;
    int lane = threadIdx.x & 31;
    int is64 = g_bat64;
    int d = 2 * warp + (lane >> 4);
    int l = lane & 15;
    if (d >= N_NODES) return;              // N_NODES even -> warp-uniform exit
    int start = g_rowptr[d], end = g_rowptr[d + 1];
    int total = end - start;
    float dvd = g_dinv[d];
    float acc = g_h2s[d * H2DIM + l];
    int iters = (total + 15) >> 4;
    int maxIters = __reduce_max_sync(0xffffffffu, iters);
    for (int t = 0; t < maxIters; t++) {
        int idx = start + t * 16 + l;
        int s = (idx < end) ? g_csrc[idx] : 0;
        int done = t * 16;
        int m = total - done; if (m > 16) m = 16; if (m < 0) m = 0;
        float a0 = 0.f, a1 = 0.f, a2 = 0.f, a3 = 0.f;
#pragma unroll
        for (int j = 0; j < 16; j += 4) {
            int s0 = __shfl_sync(0xffffffffu, s, j,     16);
            int s1 = __shfl_sync(0xffffffffu, s, j + 1, 16);
            int s2 = __shfl_sync(0xffffffffu, s, j + 2, 16);
            int s3 = __shfl_sync(0xffffffffu, s, j + 3, 16);
            if (j     < m) a0 += g_h2s[s0 * H2DIM + l];
            if (j + 1 < m) a1 += g_h2s[s1 * H2DIM + l];
            if (j + 2 < m) a2 += g_h2s[s2 * H2DIM + l];
            if (j + 3 < m) a3 += g_h2s[s3 * H2DIM + l];
        }
        acc += (a0 + a1) + (a2 + a3);
    }
    int g = clampi(load_idx(batch, d, is64), 0, N_GRAPHS - 1);
    float v = fmaxf(acc * dvd + b2[l], 0.0f);
    atomicAdd(&g_sum[g * H2DIM + l], v);
    if (l == 0) atomicAdd(&g_cnt[g], 1.0f);
}

// ---------------- 11. final: mean, FC (tf32), softmax ----------------------
__global__ void k_final(const float* __restrict__ fc_w, const float* __restrict__ fc_b,
                        float* __restrict__ out) {
    int g = blockIdx.x * blockDim.x + threadIdx.x;
    if (g >= N_GRAPHS) return;
    float inv = 1.0f / fmaxf(g_cnt[g], 1.0f);
    float p[H2DIM];
#pragma unroll
    for (int j = 0; j < H2DIM; j++) p[j] = tf32r(g_sum[g * H2DIM + j] * inv);
    float logit[NCLS];
#pragma unroll
    for (int c = 0; c < NCLS; c++) {
        float acc = 0.0f;
#pragma unroll
        for (int j = 0; j < H2DIM; j++) acc = fmaf(p[j], tf32r(fc_w[j * NCLS + c]), acc);
        logit[c] = acc + fc_b[c];
    }
    float m = logit[0];
#pragma unroll
    for (int c = 1; c < NCLS; c++) m = fmaxf(m, logit[c]);
    float s = 0.0f;
#pragma unroll
    for (int c = 0; c < NCLS; c++) { logit[c] = expf(logit[c] - m); s += logit[c]; }
    float invs = 1.0f / s;
#pragma unroll
    for (int c = 0; c < NCLS; c++) out[g * NCLS + c] = logit[c] * invs;
}

// ---------------------------------------------------------------------------
extern "C" void kernel_launch(void* const* d_in, const int* in_sizes, int n_in,
                              void* d_out, int out_size) {
    const float *x   = (n_in > 0) ? (const float*)d_in[0] : 0;
    const void  *ei  = (n_in > 1) ? d_in[1]               : 0;
    const void  *bat = (n_in > 2) ? d_in[2]               : 0;
    const float *W1  = (n_in > 3) ? (const float*)d_in[3] : 0;
    const float *b1  = (n_in > 4) ? (const float*)d_in[4] : 0;
    const float *W2  = (n_in > 5) ? (const float*)d_in[5] : 0;
    const float *b2  = (n_in > 6) ? (const float*)d_in[6] : 0;
    const float *fcw = (n_in > 7) ? (const float*)d_in[7] : 0;
    const float *fcb = (n_in > 8) ? (const float*)d_in[8] : 0;

    for (int i = 0; i < n_in; i++) {
        switch (in_sizes[i]) {
            case N_NODES * FEAT:   x   = (const float*)d_in[i]; break;
            case 2 * N_EDGES:      ei  = d_in[i];               break;
            case N_NODES:          bat = d_in[i];               break;
            case FEAT * H1DIM:     W1  = (const float*)d_in[i]; break;
            case H1DIM:            b1  = (const float*)d_in[i]; break;
            case H1DIM * H2DIM:    W2  = (const float*)d_in[i]; break;
            case H2DIM:            b2  = (const float*)d_in[i]; break;
            case H2DIM * NCLS:     fcw = (const float*)d_in[i]; break;
            case NCLS:             fcb = (const float*)d_in[i]; break;
            default: break;
        }
    }
    float* out = (float*)d_out;
    if (!x || !ei || !bat || !W1 || !b1 || !W2 || !b2 || !fcw || !fcb || !out) return;

    const int T = 256;
    k_probe   <<<1, 32>>>((const int*)ei, (const int*)bat);
    k_init    <<<(N_NODES + T - 1) / T, T>>>();
    k_deg     <<<(N_EDGES / 2 + T - 1) / T, T>>>(ei);
    k_bsum    <<<NBLK, SB>>>();
    k_bscan   <<<1, 128>>>();
    k_rowfill <<<NBLK, SB>>>();
    k_fill    <<<(N_EDGES + T - 1) / T, T>>>(ei);
    k_gemm1   <<<N_NODES / G1ROWS, 256>>>(x, W1);
    k_agg1g2  <<<(N_NODES * 32 + T - 1) / T, T>>>(b1, W2);
    k_agg2pool<<<(N_NODES / 2 * 32 + T - 1) / T, T>>>(b2, bat);
    k_final   <<<(N_GRAPHS + T - 1) / T, T>>>(fcw, fcb, out);
}